// round 11
// baseline (speedup 1.0000x reference)
#include <cuda_runtime.h>

// ---------------------------------------------------------------------------
// MS-SSIM, 4 levels, 11-tap Gaussian (sigma=1.5), VALID padding.
// X, Y: [16, 3, 512, 512] fp32. Output: 16 fp32 (1 - ms_ssim per batch).
//
// R11: R10 with the POOL plane-offset bug fixed (Xp/Yp must be offset by
// plane inside the kernel; R10 raced all planes into plane 0).
//  (a) float4-vectorized halo loads on interior tiles,
//  (b) ssim0 (+fused pool->L1) -> pool23 -> L1 || L2 || L3 on 3 streams.
// ---------------------------------------------------------------------------

#define KW 11
#define NB 16
#define NC 3

__device__ double g_acc[4 * NB];
__device__ float g_X1[NB * NC * 256 * 256];
__device__ float g_Y1[NB * NC * 256 * 256];
__device__ float g_X2[NB * NC * 128 * 128];
__device__ float g_Y2[NB * NC * 128 * 128];
__device__ float g_X3[NB * NC * 64 * 64];
__device__ float g_Y3[NB * NC * 64 * 64];

typedef unsigned long long ull;

__device__ __forceinline__ ull pk2(float lo, float hi) {
    ull r; asm("mov.b64 %0,{%1,%2};" : "=l"(r) : "f"(lo), "f"(hi)); return r;
}
__device__ __forceinline__ void up2(ull v, float& lo, float& hi) {
    asm("mov.b64 {%0,%1},%2;" : "=f"(lo), "=f"(hi) : "l"(v));
}
__device__ __forceinline__ ull fma2(ull a, ull b, ull c) {
    ull d; asm("fma.rn.f32x2 %0,%1,%2,%3;" : "=l"(d) : "l"(a), "l"(b), "l"(c));
    return d;
}
__device__ __forceinline__ ull mul2(ull a, ull b) {
    ull d; asm("mul.rn.f32x2 %0,%1,%2;" : "=l"(d) : "l"(a), "l"(b));
    return d;
}

__global__ void zero_acc_kernel() {
    int i = threadIdx.x;
    if (i < 4 * NB) g_acc[i] = 0.0;
}

// ---------------------------------------------------------------------------
// Per-level SSIM kernel. POOL: fused 2x2 avg-pool of interior patch.
// Grid: (tilesX*tilesY, NC, NB), block: TW_ threads.
// ---------------------------------------------------------------------------
template<int TW_, int TH_, bool LAST, bool POOL>
__global__ __launch_bounds__(TW_) void ssim_level_kernel(
    const float* __restrict__ X, const float* __restrict__ Y,
    float* __restrict__ Xp, float* __restrict__ Yp,
    int H, int W, int outH, int outW, int tilesX, int level)
{
    constexpr int IH_  = TH_ + KW - 1;
    constexpr int IW_  = TW_ + KW - 1;
    constexpr int IWP_ = TW_ + 12;          // divisible by 4
    constexpr int Q4   = IWP_ / 4;
    constexpr int NWARP = TW_ / 32;

    __shared__ float2 sxy[IH_][IWP_];
    __shared__ float red[NWARP];

    const int b = blockIdx.z;
    const int c = blockIdx.y;
    const int tile = blockIdx.x;
    const int tx = tile % tilesX;
    const int ty = tile / tilesX;
    const int ix0 = tx * TW_;
    const int iy0 = ty * TH_;
    const int tid = threadIdx.x;

    const size_t plane = (size_t)(b * NC + c) * H * W;
    const float* __restrict__ Xi = X + plane;
    const float* __restrict__ Yi = Y + plane;

    // ---- Phase 0: halo load ----
    if (ix0 + IWP_ <= W) {
        // Fast path: vectorized float4 rows.
        #pragma unroll 2
        for (int i = tid; i < IH_ * Q4; i += TW_) {
            int r = i / Q4;
            int q = i - r * Q4;
            int gy = min(iy0 + r, H - 1);
            const float* xrow = Xi + gy * W + ix0 + 4 * q;
            const float* yrow = Yi + gy * W + ix0 + 4 * q;
            float4 x4 = *(const float4*)xrow;
            float4 y4 = *(const float4*)yrow;
            float2* dst = &sxy[r][4 * q];
            dst[0] = make_float2(x4.x, y4.x);
            dst[1] = make_float2(x4.y, y4.y);
            dst[2] = make_float2(x4.z, y4.z);
            dst[3] = make_float2(x4.w, y4.w);
        }
    } else {
        #pragma unroll 4
        for (int i = tid; i < IH_ * IW_; i += TW_) {
            int r  = i / IW_;
            int cc = i - r * IW_;
            int gy = min(iy0 + r,  H - 1);
            int gx = min(ix0 + cc, W - 1);
            int gi = gy * W + gx;
            sxy[r][cc] = make_float2(Xi[gi], Yi[gi]);
        }
    }
    __syncthreads();

    const float G[KW] = {
        0.00102838f, 0.00759875f, 0.03600077f, 0.10936069f, 0.21300553f,
        0.26601174f,
        0.21300553f, 0.10936069f, 0.03600077f, 0.00759875f, 0.00102838f
    };
    const float C1 = 1e-4f;
    const float C2 = 9e-4f;

    ull   r01[KW];
    ull   r23[KW];
    float r4[KW];

    const int lx = tid;
    const int ox = ix0 + lx;
    const bool colOK = (ox < outW);
    float local = 0.f;

    #pragma unroll
    for (int r = 0; r < IH_; r++) {
        const ull* __restrict__ row =
            reinterpret_cast<const ull*>(&sxy[r][lx]);
        ull s01, s23; float s4;
        {
            ull v = row[0];
            ull gg = pk2(G[0], G[0]);
            s01 = mul2(gg, v);
            ull t = mul2(gg, v);
            s23 = mul2(t, v);
            float xv, yv, tl, th;
            up2(v, xv, yv); up2(t, tl, th);
            s4 = tl * yv;
            (void)xv; (void)th;
        }
        #pragma unroll
        for (int k = 1; k < KW; k++) {
            ull v = row[k];
            ull gg = pk2(G[k], G[k]);
            s01 = fma2(gg, v, s01);
            ull t = mul2(gg, v);
            s23 = fma2(t, v, s23);
            float xv, yv, tl, th;
            up2(v, xv, yv); up2(t, tl, th);
            s4 = fmaf(tl, yv, s4);
            (void)xv; (void)th;
        }
        r01[r % KW] = s01;
        r23[r % KW] = s23;
        r4[r % KW]  = s4;

        if (r >= KW - 1) {
            const int orow = r - (KW - 1);
            ull m01, m23; float m4;
            {
                int idx = orow % KW;
                ull gg = pk2(G[0], G[0]);
                m01 = mul2(gg, r01[idx]);
                m23 = mul2(gg, r23[idx]);
                m4  = G[0] * r4[idx];
            }
            #pragma unroll
            for (int k = 1; k < KW; k++) {
                int idx = (orow + k) % KW;
                ull gg = pk2(G[k], G[k]);
                m01 = fma2(gg, r01[idx], m01);
                m23 = fma2(gg, r23[idx], m23);
                m4  = fmaf(G[k], r4[idx], m4);
            }
            int oy = iy0 + orow;
            if (colOK && oy < outH) {
                float mu1, mu2, xx, yy;
                up2(m01, mu1, mu2);
                up2(m23, xx, yy);
                float s1q = xx - mu1 * mu1;
                float s2q = yy - mu2 * mu2;
                float s12 = m4 - mu1 * mu2;
                float cs = __fdividef(2.f * s12 + C2, s1q + s2q + C2);
                cs = fmaxf(cs, 0.f);
                if (LAST) {
                    float lum = __fdividef(2.f * mu1 * mu2 + C1,
                                           mu1 * mu1 + mu2 * mu2 + C1);
                    local = fmaf(lum, cs, local);
                } else {
                    local += cs;
                }
            }
        }
    }

    // ---- Fused 2x2 pool of interior patch (plane offset FIXED) ----
    if (POOL) {
        const int oW = W >> 1;
        const int oHp = H >> 1;
        const int pgy0 = iy0 >> 1;
        const int pgx0 = ix0 >> 1;
        constexpr int PW = TW_ / 2;
        constexpr int ITER = (TH_ / 2) * PW / TW_;
        float* __restrict__ Xo = Xp + (size_t)(b * NC + c) * oW * oHp;
        float* __restrict__ Yo = Yp + (size_t)(b * NC + c) * oW * oHp;
        #pragma unroll
        for (int i = 0; i < ITER; i++) {
            int idx = tid + i * TW_;
            int py = idx / PW;
            int px = idx % PW;
            float2 a  = sxy[2 * py][2 * px];
            float2 bb = sxy[2 * py][2 * px + 1];
            float2 cc = sxy[2 * py + 1][2 * px];
            float2 dd = sxy[2 * py + 1][2 * px + 1];
            float xv = 0.25f * ((a.x + bb.x) + (cc.x + dd.x));
            float yv = 0.25f * ((a.y + bb.y) + (cc.y + dd.y));
            size_t o = (size_t)(pgy0 + py) * oW + (pgx0 + px);
            Xo[o] = xv;
            Yo[o] = yv;
        }
    }

    #pragma unroll
    for (int s = 16; s > 0; s >>= 1)
        local += __shfl_down_sync(0xffffffffu, local, s);
    if ((tid & 31) == 0) red[tid >> 5] = local;
    __syncthreads();
    if (tid == 0) {
        float t = 0.f;
        #pragma unroll
        for (int w = 0; w < NWARP; w++) t += red[w];
        atomicAdd(&g_acc[level * NB + b], (double)t);
    }
}

// ---------------------------------------------------------------------------
// Pool L1 -> L2, L3. 256 threads per 32x32 patch of L1.
// Grid: 48 planes * 64 patches.
// ---------------------------------------------------------------------------
__global__ __launch_bounds__(256) void pool23_kernel()
{
    __shared__ float2 s2[16][17];

    const int plane = blockIdx.x >> 6;
    const int patch = blockIdx.x & 63;
    const int px = patch & 7, py = patch >> 3;
    const int tid = threadIdx.x;
    const int tx = tid & 15, ty = tid >> 4;

    const float* X1 = g_X1 + (size_t)plane * 256 * 256;
    const float* Y1 = g_Y1 + (size_t)plane * 256 * 256;

    const int gy = py * 32 + 2 * ty;
    const int gx = px * 32 + 2 * tx;
    const int o0 = gy * 256 + gx;
    float2 xa = *(const float2*)(X1 + o0);
    float2 xb = *(const float2*)(X1 + o0 + 256);
    float2 ya = *(const float2*)(Y1 + o0);
    float2 yb = *(const float2*)(Y1 + o0 + 256);
    float xv = 0.25f * ((xa.x + xa.y) + (xb.x + xb.y));
    float yv = 0.25f * ((ya.x + ya.y) + (yb.x + yb.y));

    g_X2[(size_t)plane * 128 * 128 + (py * 16 + ty) * 128 + (px * 16 + tx)] = xv;
    g_Y2[(size_t)plane * 128 * 128 + (py * 16 + ty) * 128 + (px * 16 + tx)] = yv;
    s2[ty][tx] = make_float2(xv, yv);
    __syncthreads();

    if (tid < 64) {
        int t3x = tid & 7, t3y = tid >> 3;
        float2 a = s2[2 * t3y][2 * t3x];
        float2 b = s2[2 * t3y][2 * t3x + 1];
        float2 c = s2[2 * t3y + 1][2 * t3x];
        float2 d = s2[2 * t3y + 1][2 * t3x + 1];
        float x3 = 0.25f * ((a.x + b.x) + (c.x + d.x));
        float y3 = 0.25f * ((a.y + b.y) + (c.y + d.y));
        g_X3[(size_t)plane * 64 * 64 + (py * 8 + t3y) * 64 + (px * 8 + t3x)] = x3;
        g_Y3[(size_t)plane * 64 * 64 + (py * 8 + t3y) * 64 + (px * 8 + t3x)] = y3;
    }
}

__global__ void finalize_kernel(float* __restrict__ out) {
    int b = threadIdx.x;
    if (b >= NB) return;
    const double counts[4] = {
        3.0 * 502.0 * 502.0,
        3.0 * 246.0 * 246.0,
        3.0 * 118.0 * 118.0,
        3.0 * 54.0  * 54.0
    };
    const double wraw[4] = {0.0448, 0.2856, 0.3001, 0.2363};
    const double wsum = 0.0448 + 0.2856 + 0.3001 + 0.2363;
    double s = 0.0;
    #pragma unroll
    for (int l = 0; l < 4; l++) {
        double v = g_acc[l * NB + b] / counts[l];
        v = v > 1e-8 ? v : 1e-8;
        s += (wraw[l] / wsum) * log(v);
    }
    out[b] = (float)(1.0 - exp(s));
}

// Streams/events created at static init (no device-memory APIs).
struct GraphResources {
    cudaStream_t s3, s4;
    cudaEvent_t eP, eJ2, eJ3;
    GraphResources() {
        cudaStreamCreateWithFlags(&s3, cudaStreamNonBlocking);
        cudaStreamCreateWithFlags(&s4, cudaStreamNonBlocking);
        cudaEventCreateWithFlags(&eP, cudaEventDisableTiming);
        cudaEventCreateWithFlags(&eJ2, cudaEventDisableTiming);
        cudaEventCreateWithFlags(&eJ3, cudaEventDisableTiming);
    }
};
static GraphResources g_res;

extern "C" void kernel_launch(void* const* d_in, const int* in_sizes, int n_in,
                              void* d_out, int out_size)
{
    const float* X = (const float*)d_in[0];
    const float* Y = (const float*)d_in[1];
    float* out = (float*)d_out;
    (void)in_sizes; (void)n_in; (void)out_size;

    static float *pX1 = nullptr, *pY1 = nullptr, *pX2 = nullptr, *pY2 = nullptr,
                 *pX3 = nullptr, *pY3 = nullptr;
    if (!pX1) {
        cudaGetSymbolAddress((void**)&pX1, g_X1);
        cudaGetSymbolAddress((void**)&pY1, g_Y1);
        cudaGetSymbolAddress((void**)&pX2, g_X2);
        cudaGetSymbolAddress((void**)&pY2, g_Y2);
        cudaGetSymbolAddress((void**)&pX3, g_X3);
        cudaGetSymbolAddress((void**)&pY3, g_Y3);
    }

    zero_acc_kernel<<<1, 64>>>();

    // ---- ssim0 with fused pool -> L1 (serial critical path) ----
    {
        dim3 grid(4 * 16, NC, NB);    // 128x32 tiles over 502x502
        ssim_level_kernel<128, 32, false, true><<<grid, 128>>>(
            X, Y, pX1, pY1, 512, 512, 502, 502, 4, 0);
    }

    // ---- pool23: L1 -> L2, L3 ----
    pool23_kernel<<<NB * NC * 64, 256>>>();
    cudaEventRecord(g_res.eP, 0);
    cudaStreamWaitEvent(g_res.s3, g_res.eP, 0);
    cudaStreamWaitEvent(g_res.s4, g_res.eP, 0);

    // ---- L1 on stream 0 (largest), L2/L3 concurrent on side streams ----
    {
        dim3 grid(2 * 8, NC, NB);     // L1: 128x32 tiles over 246x246
        ssim_level_kernel<128, 32, false, false><<<grid, 128>>>(
            pX1, pY1, nullptr, nullptr, 256, 256, 246, 246, 2, 1);
    }
    {
        dim3 grid(2 * 8, NC, NB);     // L2: 64x16 tiles over 118x118
        ssim_level_kernel<64, 16, false, false><<<grid, 64, 0, g_res.s3>>>(
            pX2, pY2, nullptr, nullptr, 128, 128, 118, 118, 2, 2);
    }
    {
        dim3 grid(1 * 4, NC, NB);     // L3: 64x16 tiles over 54x54
        ssim_level_kernel<64, 16, true, false><<<grid, 64, 0, g_res.s4>>>(
            pX3, pY3, nullptr, nullptr, 64, 64, 54, 54, 1, 3);
    }
    cudaEventRecord(g_res.eJ2, g_res.s3);
    cudaEventRecord(g_res.eJ3, g_res.s4);
    cudaStreamWaitEvent(0, g_res.eJ2, 0);
    cudaStreamWaitEvent(0, g_res.eJ3, 0);

    finalize_kernel<<<1, 32>>>(out);
}

// round 12
// speedup vs baseline: 1.0153x; 1.0153x over previous
#include <cuda_runtime.h>

// ---------------------------------------------------------------------------
// MS-SSIM, 4 levels, 11-tap Gaussian (sigma=1.5), VALID padding.
// X, Y: [16, 3, 512, 512] fp32. Output: 16 fp32 (1 - ms_ssim per batch).
//
// R12: exact R4 champion structure (serial levels, fused pool in L0) +
//  (a) __launch_bounds__(128, 6): force regs <= ~85 -> 24 warps/SM,
//  (b) float4-vectorized interior halo loads (cuts ALU address math).
// ---------------------------------------------------------------------------

#define KW 11
#define NB 16
#define NC 3

__device__ double g_acc[4 * NB];
__device__ float g_X1[NB * NC * 256 * 256];
__device__ float g_Y1[NB * NC * 256 * 256];
__device__ float g_X2[NB * NC * 128 * 128];
__device__ float g_Y2[NB * NC * 128 * 128];
__device__ float g_X3[NB * NC * 64 * 64];
__device__ float g_Y3[NB * NC * 64 * 64];

typedef unsigned long long ull;

__device__ __forceinline__ ull pk2(float lo, float hi) {
    ull r; asm("mov.b64 %0,{%1,%2};" : "=l"(r) : "f"(lo), "f"(hi)); return r;
}
__device__ __forceinline__ void up2(ull v, float& lo, float& hi) {
    asm("mov.b64 {%0,%1},%2;" : "=f"(lo), "=f"(hi) : "l"(v));
}
__device__ __forceinline__ ull fma2(ull a, ull b, ull c) {
    ull d; asm("fma.rn.f32x2 %0,%1,%2,%3;" : "=l"(d) : "l"(a), "l"(b), "l"(c));
    return d;
}
__device__ __forceinline__ ull mul2(ull a, ull b) {
    ull d; asm("mul.rn.f32x2 %0,%1,%2;" : "=l"(d) : "l"(a), "l"(b));
    return d;
}

__global__ void zero_acc_kernel() {
    int i = threadIdx.x;
    if (i < 4 * NB) g_acc[i] = 0.0;
}

// ---------------------------------------------------------------------------
// Per-level SSIM kernel. POOL: fused 2x2 avg-pool of interior patch.
// Grid: (tilesX*tilesY, NC, NB), block: TW_ threads.
// MINB: min blocks/SM — the register-pressure lever.
// ---------------------------------------------------------------------------
template<int TW_, int TH_, bool LAST, bool POOL, int MINB>
__global__ __launch_bounds__(TW_, MINB) void ssim_level_kernel(
    const float* __restrict__ X, const float* __restrict__ Y,
    float* __restrict__ Xp, float* __restrict__ Yp,
    int H, int W, int outH, int outW, int tilesX, int level)
{
    constexpr int IH_  = TH_ + KW - 1;
    constexpr int IW_  = TW_ + KW - 1;
    constexpr int IWP_ = TW_ + 12;          // divisible by 4
    constexpr int Q4   = IWP_ / 4;
    constexpr int NWARP = TW_ / 32;

    __shared__ float2 sxy[IH_][IWP_];
    __shared__ float red[NWARP];

    const int b = blockIdx.z;
    const int c = blockIdx.y;
    const int tile = blockIdx.x;
    const int tx = tile % tilesX;
    const int ty = tile / tilesX;
    const int ix0 = tx * TW_;
    const int iy0 = ty * TH_;
    const int tid = threadIdx.x;

    const size_t plane = (size_t)(b * NC + c) * H * W;
    const float* __restrict__ Xi = X + plane;
    const float* __restrict__ Yi = Y + plane;

    // ---- Phase 0: halo load ----
    if (ix0 + IWP_ <= W) {
        #pragma unroll 2
        for (int i = tid; i < IH_ * Q4; i += TW_) {
            int r = i / Q4;
            int q = i - r * Q4;
            int gy = min(iy0 + r, H - 1);
            const float* xrow = Xi + gy * W + ix0 + 4 * q;
            const float* yrow = Yi + gy * W + ix0 + 4 * q;
            float4 x4 = *(const float4*)xrow;
            float4 y4 = *(const float4*)yrow;
            float2* dst = &sxy[r][4 * q];
            dst[0] = make_float2(x4.x, y4.x);
            dst[1] = make_float2(x4.y, y4.y);
            dst[2] = make_float2(x4.z, y4.z);
            dst[3] = make_float2(x4.w, y4.w);
        }
    } else {
        #pragma unroll 4
        for (int i = tid; i < IH_ * IW_; i += TW_) {
            int r  = i / IW_;
            int cc = i - r * IW_;
            int gy = min(iy0 + r,  H - 1);
            int gx = min(ix0 + cc, W - 1);
            int gi = gy * W + gx;
            sxy[r][cc] = make_float2(Xi[gi], Yi[gi]);
        }
    }
    __syncthreads();

    const float G[KW] = {
        0.00102838f, 0.00759875f, 0.03600077f, 0.10936069f, 0.21300553f,
        0.26601174f,
        0.21300553f, 0.10936069f, 0.03600077f, 0.00759875f, 0.00102838f
    };
    const float C1 = 1e-4f;
    const float C2 = 9e-4f;

    ull   r01[KW];
    ull   r23[KW];
    float r4[KW];

    const int lx = tid;
    const int ox = ix0 + lx;
    const bool colOK = (ox < outW);
    float local = 0.f;

    #pragma unroll
    for (int r = 0; r < IH_; r++) {
        const ull* __restrict__ row =
            reinterpret_cast<const ull*>(&sxy[r][lx]);
        ull s01, s23; float s4;
        {
            ull v = row[0];
            ull gg = pk2(G[0], G[0]);
            s01 = mul2(gg, v);
            ull t = mul2(gg, v);
            s23 = mul2(t, v);
            float xv, yv, tl, th;
            up2(v, xv, yv); up2(t, tl, th);
            s4 = tl * yv;
            (void)xv; (void)th;
        }
        #pragma unroll
        for (int k = 1; k < KW; k++) {
            ull v = row[k];
            ull gg = pk2(G[k], G[k]);
            s01 = fma2(gg, v, s01);
            ull t = mul2(gg, v);
            s23 = fma2(t, v, s23);
            float xv, yv, tl, th;
            up2(v, xv, yv); up2(t, tl, th);
            s4 = fmaf(tl, yv, s4);
            (void)xv; (void)th;
        }
        r01[r % KW] = s01;
        r23[r % KW] = s23;
        r4[r % KW]  = s4;

        if (r >= KW - 1) {
            const int orow = r - (KW - 1);
            ull m01, m23; float m4;
            {
                int idx = orow % KW;
                ull gg = pk2(G[0], G[0]);
                m01 = mul2(gg, r01[idx]);
                m23 = mul2(gg, r23[idx]);
                m4  = G[0] * r4[idx];
            }
            #pragma unroll
            for (int k = 1; k < KW; k++) {
                int idx = (orow + k) % KW;
                ull gg = pk2(G[k], G[k]);
                m01 = fma2(gg, r01[idx], m01);
                m23 = fma2(gg, r23[idx], m23);
                m4  = fmaf(G[k], r4[idx], m4);
            }
            int oy = iy0 + orow;
            if (colOK && oy < outH) {
                float mu1, mu2, xx, yy;
                up2(m01, mu1, mu2);
                up2(m23, xx, yy);
                float s1q = xx - mu1 * mu1;
                float s2q = yy - mu2 * mu2;
                float s12 = m4 - mu1 * mu2;
                float cs = __fdividef(2.f * s12 + C2, s1q + s2q + C2);
                cs = fmaxf(cs, 0.f);
                if (LAST) {
                    float lum = __fdividef(2.f * mu1 * mu2 + C1,
                                           mu1 * mu1 + mu2 * mu2 + C1);
                    local = fmaf(lum, cs, local);
                } else {
                    local += cs;
                }
            }
        }
    }

    // ---- Fused 2x2 pool of interior patch (per-plane offset applied) ----
    if (POOL) {
        const int oW = W >> 1;
        const int oHp = H >> 1;
        const int pgy0 = iy0 >> 1;
        const int pgx0 = ix0 >> 1;
        constexpr int PW = TW_ / 2;
        constexpr int ITER = (TH_ / 2) * PW / TW_;
        float* __restrict__ Xo = Xp + (size_t)(b * NC + c) * oW * oHp;
        float* __restrict__ Yo = Yp + (size_t)(b * NC + c) * oW * oHp;
        #pragma unroll
        for (int i = 0; i < ITER; i++) {
            int idx = tid + i * TW_;
            int py = idx / PW;
            int px = idx % PW;
            float2 a  = sxy[2 * py][2 * px];
            float2 bb = sxy[2 * py][2 * px + 1];
            float2 cc = sxy[2 * py + 1][2 * px];
            float2 dd = sxy[2 * py + 1][2 * px + 1];
            float xv = 0.25f * ((a.x + bb.x) + (cc.x + dd.x));
            float yv = 0.25f * ((a.y + bb.y) + (cc.y + dd.y));
            size_t o = (size_t)(pgy0 + py) * oW + (pgx0 + px);
            Xo[o] = xv;
            Yo[o] = yv;
        }
    }

    #pragma unroll
    for (int s = 16; s > 0; s >>= 1)
        local += __shfl_down_sync(0xffffffffu, local, s);
    if ((tid & 31) == 0) red[tid >> 5] = local;
    __syncthreads();
    if (tid == 0) {
        float t = 0.f;
        #pragma unroll
        for (int w = 0; w < NWARP; w++) t += red[w];
        atomicAdd(&g_acc[level * NB + b], (double)t);
    }
}

__global__ void finalize_kernel(float* __restrict__ out) {
    int b = threadIdx.x;
    if (b >= NB) return;
    const double counts[4] = {
        3.0 * 502.0 * 502.0,
        3.0 * 246.0 * 246.0,
        3.0 * 118.0 * 118.0,
        3.0 * 54.0  * 54.0
    };
    const double wraw[4] = {0.0448, 0.2856, 0.3001, 0.2363};
    const double wsum = 0.0448 + 0.2856 + 0.3001 + 0.2363;
    double s = 0.0;
    #pragma unroll
    for (int l = 0; l < 4; l++) {
        double v = g_acc[l * NB + b] / counts[l];
        v = v > 1e-8 ? v : 1e-8;
        s += (wraw[l] / wsum) * log(v);
    }
    out[b] = (float)(1.0 - exp(s));
}

static inline int cdiv(int a, int b) { return (a + b - 1) / b; }

extern "C" void kernel_launch(void* const* d_in, const int* in_sizes, int n_in,
                              void* d_out, int out_size)
{
    const float* X = (const float*)d_in[0];
    const float* Y = (const float*)d_in[1];
    float* out = (float*)d_out;
    (void)in_sizes; (void)n_in; (void)out_size;

    static float *pX1 = nullptr, *pY1 = nullptr, *pX2 = nullptr, *pY2 = nullptr,
                 *pX3 = nullptr, *pY3 = nullptr;
    if (!pX1) {
        cudaGetSymbolAddress((void**)&pX1, g_X1);
        cudaGetSymbolAddress((void**)&pY1, g_Y1);
        cudaGetSymbolAddress((void**)&pX2, g_X2);
        cudaGetSymbolAddress((void**)&pY2, g_Y2);
        cudaGetSymbolAddress((void**)&pX3, g_X3);
        cudaGetSymbolAddress((void**)&pY3, g_Y3);
    }

    zero_acc_kernel<<<1, 64>>>();

    // Level 0: 512 -> out 502, fused pool to 256. Tiles 128x32.
    {
        dim3 grid(4 * 16, NC, NB);
        ssim_level_kernel<128, 32, false, true, 6><<<grid, 128>>>(
            X, Y, pX1, pY1, 512, 512, 502, 502, 4, 0);
    }
    // Level 1: 256 -> out 246, fused pool to 128. Tiles 128x32.
    {
        dim3 grid(2 * 8, NC, NB);
        ssim_level_kernel<128, 32, false, true, 6><<<grid, 128>>>(
            pX1, pY1, pX2, pY2, 256, 256, 246, 246, 2, 1);
    }
    // Level 2: 128 -> out 118, fused pool to 64. Tiles 64x16.
    {
        dim3 grid(2 * 8, NC, NB);
        ssim_level_kernel<64, 16, false, true, 12><<<grid, 64>>>(
            pX2, pY2, pX3, pY3, 128, 128, 118, 118, 2, 2);
    }
    // Level 3: 64 -> out 54, last (ssim map), no pool. Tiles 64x16.
    {
        dim3 grid(1 * 4, NC, NB);
        ssim_level_kernel<64, 16, true, false, 12><<<grid, 64>>>(
            pX3, pY3, nullptr, nullptr, 64, 64, 54, 54, 1, 3);
    }

    finalize_kernel<<<1, 32>>>(out);
}

// round 13
// speedup vs baseline: 1.0771x; 1.0609x over previous
#include <cuda_runtime.h>

// ---------------------------------------------------------------------------
// MS-SSIM, 4 levels, 11-tap Gaussian (sigma=1.5), VALID padding.
// X, Y: [16, 3, 512, 512] fp32. Output: 16 fp32 (1 - ms_ssim per batch).
//
// R13: R4 serial structure. L0/L1 tiles 128x22 (smem 35.3KB -> 5 blocks/SM,
// +25% warps) with launch_bounds(128,5); fused pool handles the non-dividing
// tile height by letting the last tile row pool its halo rows. L2/L3 = R4.
// ---------------------------------------------------------------------------

#define KW 11
#define NB 16
#define NC 3

__device__ double g_acc[4 * NB];
__device__ float g_X1[NB * NC * 256 * 256];
__device__ float g_Y1[NB * NC * 256 * 256];
__device__ float g_X2[NB * NC * 128 * 128];
__device__ float g_Y2[NB * NC * 128 * 128];
__device__ float g_X3[NB * NC * 64 * 64];
__device__ float g_Y3[NB * NC * 64 * 64];

typedef unsigned long long ull;

__device__ __forceinline__ ull pk2(float lo, float hi) {
    ull r; asm("mov.b64 %0,{%1,%2};" : "=l"(r) : "f"(lo), "f"(hi)); return r;
}
__device__ __forceinline__ void up2(ull v, float& lo, float& hi) {
    asm("mov.b64 {%0,%1},%2;" : "=f"(lo), "=f"(hi) : "l"(v));
}
__device__ __forceinline__ ull fma2(ull a, ull b, ull c) {
    ull d; asm("fma.rn.f32x2 %0,%1,%2,%3;" : "=l"(d) : "l"(a), "l"(b), "l"(c));
    return d;
}
__device__ __forceinline__ ull mul2(ull a, ull b) {
    ull d; asm("mul.rn.f32x2 %0,%1,%2;" : "=l"(d) : "l"(a), "l"(b));
    return d;
}

__global__ void zero_acc_kernel() {
    int i = threadIdx.x;
    if (i < 4 * NB) g_acc[i] = 0.0;
}

// ---------------------------------------------------------------------------
// Per-level SSIM kernel. POOL: fused 2x2 avg-pool; the last tile row pools
// all remaining image rows (they live in its halo, unclamped).
// Grid: (tilesX*tilesY, NC, NB), block: TW_ threads.
// ---------------------------------------------------------------------------
template<int TW_, int TH_, bool LAST, bool POOL, int MINB>
__global__ __launch_bounds__(TW_, MINB) void ssim_level_kernel(
    const float* __restrict__ X, const float* __restrict__ Y,
    float* __restrict__ Xp, float* __restrict__ Yp,
    int H, int W, int outH, int outW, int tilesX, int level)
{
    constexpr int IH_  = TH_ + KW - 1;
    constexpr int IW_  = TW_ + KW - 1;
    constexpr int IWP_ = TW_ + 10;          // == IW_ rounded to even
    constexpr int NWARP = TW_ / 32;

    __shared__ float2 sxy[IH_][IWP_];
    __shared__ float red[NWARP];

    const int b = blockIdx.z;
    const int c = blockIdx.y;
    const int tile = blockIdx.x;
    const int tx = tile % tilesX;
    const int ty = tile / tilesX;
    const int ix0 = tx * TW_;
    const int iy0 = ty * TH_;
    const int tid = threadIdx.x;

    const size_t plane = (size_t)(b * NC + c) * H * W;
    const float* __restrict__ Xi = X + plane;
    const float* __restrict__ Yi = Y + plane;

    // ---- Phase 0: cooperative halo load (clamped) ----
    #pragma unroll 4
    for (int i = tid; i < IH_ * IW_; i += TW_) {
        int r  = i / IW_;
        int cc = i - r * IW_;
        int gy = min(iy0 + r,  H - 1);
        int gx = min(ix0 + cc, W - 1);
        int gi = gy * W + gx;
        sxy[r][cc] = make_float2(Xi[gi], Yi[gi]);
    }
    __syncthreads();

    const float G[KW] = {
        0.00102838f, 0.00759875f, 0.03600077f, 0.10936069f, 0.21300553f,
        0.26601174f,
        0.21300553f, 0.10936069f, 0.03600077f, 0.00759875f, 0.00102838f
    };
    const float C1 = 1e-4f;
    const float C2 = 9e-4f;

    ull   r01[KW];
    ull   r23[KW];
    float r4[KW];

    const int lx = tid;
    const int ox = ix0 + lx;
    const bool colOK = (ox < outW);
    float local = 0.f;

    #pragma unroll
    for (int r = 0; r < IH_; r++) {
        const ull* __restrict__ row =
            reinterpret_cast<const ull*>(&sxy[r][lx]);
        ull s01, s23; float s4;
        {
            ull v = row[0];
            ull gg = pk2(G[0], G[0]);
            s01 = mul2(gg, v);
            ull t = mul2(gg, v);
            s23 = mul2(t, v);
            float xv, yv, tl, th;
            up2(v, xv, yv); up2(t, tl, th);
            s4 = tl * yv;
            (void)xv; (void)th;
        }
        #pragma unroll
        for (int k = 1; k < KW; k++) {
            ull v = row[k];
            ull gg = pk2(G[k], G[k]);
            s01 = fma2(gg, v, s01);
            ull t = mul2(gg, v);
            s23 = fma2(t, v, s23);
            float xv, yv, tl, th;
            up2(v, xv, yv); up2(t, tl, th);
            s4 = fmaf(tl, yv, s4);
            (void)xv; (void)th;
        }
        r01[r % KW] = s01;
        r23[r % KW] = s23;
        r4[r % KW]  = s4;

        if (r >= KW - 1) {
            const int orow = r - (KW - 1);
            ull m01, m23; float m4;
            {
                int idx = orow % KW;
                ull gg = pk2(G[0], G[0]);
                m01 = mul2(gg, r01[idx]);
                m23 = mul2(gg, r23[idx]);
                m4  = G[0] * r4[idx];
            }
            #pragma unroll
            for (int k = 1; k < KW; k++) {
                int idx = (orow + k) % KW;
                ull gg = pk2(G[k], G[k]);
                m01 = fma2(gg, r01[idx], m01);
                m23 = fma2(gg, r23[idx], m23);
                m4  = fmaf(G[k], r4[idx], m4);
            }
            int oy = iy0 + orow;
            if (colOK && oy < outH) {
                float mu1, mu2, xx, yy;
                up2(m01, mu1, mu2);
                up2(m23, xx, yy);
                float s1q = xx - mu1 * mu1;
                float s2q = yy - mu2 * mu2;
                float s12 = m4 - mu1 * mu2;
                float cs = __fdividef(2.f * s12 + C2, s1q + s2q + C2);
                cs = fmaxf(cs, 0.f);
                if (LAST) {
                    float lum = __fdividef(2.f * mu1 * mu2 + C1,
                                           mu1 * mu1 + mu2 * mu2 + C1);
                    local = fmaf(lum, cs, local);
                } else {
                    local += cs;
                }
            }
        }
    }

    // ---- Fused 2x2 pool. Last tile row pools all remaining rows (<= IH_).
    if (POOL) {
        const int oW = W >> 1;
        const int oHp = H >> 1;
        const int pgy0 = iy0 >> 1;
        const int pgx0 = ix0 >> 1;
        constexpr int PW = TW_ / 2;
        const int tilesY = (int)(gridDim.x) / tilesX;
        const int nin = (ty == tilesY - 1) ? (H - iy0) : TH_;
        const int npool = nin >> 1;
        float* __restrict__ Xo = Xp + (size_t)(b * NC + c) * oW * oHp;
        float* __restrict__ Yo = Yp + (size_t)(b * NC + c) * oW * oHp;
        for (int idx = tid; idx < npool * PW; idx += TW_) {
            int py = idx / PW;
            int px = idx % PW;
            float2 a  = sxy[2 * py][2 * px];
            float2 bb = sxy[2 * py][2 * px + 1];
            float2 cc = sxy[2 * py + 1][2 * px];
            float2 dd = sxy[2 * py + 1][2 * px + 1];
            float xv = 0.25f * ((a.x + bb.x) + (cc.x + dd.x));
            float yv = 0.25f * ((a.y + bb.y) + (cc.y + dd.y));
            size_t o = (size_t)(pgy0 + py) * oW + (pgx0 + px);
            Xo[o] = xv;
            Yo[o] = yv;
        }
    }

    #pragma unroll
    for (int s = 16; s > 0; s >>= 1)
        local += __shfl_down_sync(0xffffffffu, local, s);
    if ((tid & 31) == 0) red[tid >> 5] = local;
    __syncthreads();
    if (tid == 0) {
        float t = 0.f;
        #pragma unroll
        for (int w = 0; w < NWARP; w++) t += red[w];
        atomicAdd(&g_acc[level * NB + b], (double)t);
    }
}

__global__ void finalize_kernel(float* __restrict__ out) {
    int b = threadIdx.x;
    if (b >= NB) return;
    const double counts[4] = {
        3.0 * 502.0 * 502.0,
        3.0 * 246.0 * 246.0,
        3.0 * 118.0 * 118.0,
        3.0 * 54.0  * 54.0
    };
    const double wraw[4] = {0.0448, 0.2856, 0.3001, 0.2363};
    const double wsum = 0.0448 + 0.2856 + 0.3001 + 0.2363;
    double s = 0.0;
    #pragma unroll
    for (int l = 0; l < 4; l++) {
        double v = g_acc[l * NB + b] / counts[l];
        v = v > 1e-8 ? v : 1e-8;
        s += (wraw[l] / wsum) * log(v);
    }
    out[b] = (float)(1.0 - exp(s));
}

extern "C" void kernel_launch(void* const* d_in, const int* in_sizes, int n_in,
                              void* d_out, int out_size)
{
    const float* X = (const float*)d_in[0];
    const float* Y = (const float*)d_in[1];
    float* out = (float*)d_out;
    (void)in_sizes; (void)n_in; (void)out_size;

    static float *pX1 = nullptr, *pY1 = nullptr, *pX2 = nullptr, *pY2 = nullptr,
                 *pX3 = nullptr, *pY3 = nullptr;
    if (!pX1) {
        cudaGetSymbolAddress((void**)&pX1, g_X1);
        cudaGetSymbolAddress((void**)&pY1, g_Y1);
        cudaGetSymbolAddress((void**)&pX2, g_X2);
        cudaGetSymbolAddress((void**)&pY2, g_Y2);
        cudaGetSymbolAddress((void**)&pX3, g_X3);
        cudaGetSymbolAddress((void**)&pY3, g_Y3);
    }

    zero_acc_kernel<<<1, 64>>>();

    // Level 0: 512 -> out 502, fused pool to 256. Tiles 128x22 (5 blocks/SM).
    {
        dim3 grid(4 * 23, NC, NB);     // tilesX=4, tilesY=23 (23*22=506)
        ssim_level_kernel<128, 22, false, true, 5><<<grid, 128>>>(
            X, Y, pX1, pY1, 512, 512, 502, 502, 4, 0);
    }
    // Level 1: 256 -> out 246, fused pool to 128. Tiles 128x22.
    {
        dim3 grid(2 * 12, NC, NB);     // tilesX=2, tilesY=12 (12*22=264)
        ssim_level_kernel<128, 22, false, true, 5><<<grid, 128>>>(
            pX1, pY1, pX2, pY2, 256, 256, 246, 246, 2, 1);
    }
    // Level 2: 128 -> out 118, fused pool to 64. Tiles 64x16 (as R4).
    {
        dim3 grid(2 * 8, NC, NB);
        ssim_level_kernel<64, 16, false, true, 4><<<grid, 64>>>(
            pX2, pY2, pX3, pY3, 128, 128, 118, 118, 2, 2);
    }
    // Level 3: 64 -> out 54, last (ssim map), no pool. Tiles 64x16 (as R4).
    {
        dim3 grid(1 * 4, NC, NB);
        ssim_level_kernel<64, 16, true, false, 4><<<grid, 64>>>(
            pX3, pY3, nullptr, nullptr, 64, 64, 54, 54, 1, 3);
    }

    finalize_kernel<<<1, 32>>>(out);
}

// round 14
// speedup vs baseline: 1.1008x; 1.0221x over previous
#include <cuda_runtime.h>

// ---------------------------------------------------------------------------
// MS-SSIM, 4 levels, 11-tap Gaussian (sigma=1.5), VALID padding.
// X, Y: [16, 3, 512, 512] fp32. Output: 16 fp32 (1 - ms_ssim per batch).
//
// R14: R13 (L0/L1 tiles 128x22, 5 blocks/SM) with L2/L3 launch bounds
// restored to MINB=12 (R13's MINB=4 let ptxas bloat them to 206 regs and
// slowed L2 from 14.8 to 20.5 us).
// ---------------------------------------------------------------------------

#define KW 11
#define NB 16
#define NC 3

__device__ double g_acc[4 * NB];
__device__ float g_X1[NB * NC * 256 * 256];
__device__ float g_Y1[NB * NC * 256 * 256];
__device__ float g_X2[NB * NC * 128 * 128];
__device__ float g_Y2[NB * NC * 128 * 128];
__device__ float g_X3[NB * NC * 64 * 64];
__device__ float g_Y3[NB * NC * 64 * 64];

typedef unsigned long long ull;

__device__ __forceinline__ ull pk2(float lo, float hi) {
    ull r; asm("mov.b64 %0,{%1,%2};" : "=l"(r) : "f"(lo), "f"(hi)); return r;
}
__device__ __forceinline__ void up2(ull v, float& lo, float& hi) {
    asm("mov.b64 {%0,%1},%2;" : "=f"(lo), "=f"(hi) : "l"(v));
}
__device__ __forceinline__ ull fma2(ull a, ull b, ull c) {
    ull d; asm("fma.rn.f32x2 %0,%1,%2,%3;" : "=l"(d) : "l"(a), "l"(b), "l"(c));
    return d;
}
__device__ __forceinline__ ull mul2(ull a, ull b) {
    ull d; asm("mul.rn.f32x2 %0,%1,%2;" : "=l"(d) : "l"(a), "l"(b));
    return d;
}

__global__ void zero_acc_kernel() {
    int i = threadIdx.x;
    if (i < 4 * NB) g_acc[i] = 0.0;
}

// ---------------------------------------------------------------------------
// Per-level SSIM kernel. POOL: fused 2x2 avg-pool; the last tile row pools
// all remaining image rows (they live in its halo, unclamped).
// Grid: (tilesX*tilesY, NC, NB), block: TW_ threads.
// ---------------------------------------------------------------------------
template<int TW_, int TH_, bool LAST, bool POOL, int MINB>
__global__ __launch_bounds__(TW_, MINB) void ssim_level_kernel(
    const float* __restrict__ X, const float* __restrict__ Y,
    float* __restrict__ Xp, float* __restrict__ Yp,
    int H, int W, int outH, int outW, int tilesX, int level)
{
    constexpr int IH_  = TH_ + KW - 1;
    constexpr int IW_  = TW_ + KW - 1;
    constexpr int IWP_ = TW_ + 10;          // == IW_ rounded to even
    constexpr int NWARP = TW_ / 32;

    __shared__ float2 sxy[IH_][IWP_];
    __shared__ float red[NWARP];

    const int b = blockIdx.z;
    const int c = blockIdx.y;
    const int tile = blockIdx.x;
    const int tx = tile % tilesX;
    const int ty = tile / tilesX;
    const int ix0 = tx * TW_;
    const int iy0 = ty * TH_;
    const int tid = threadIdx.x;

    const size_t plane = (size_t)(b * NC + c) * H * W;
    const float* __restrict__ Xi = X + plane;
    const float* __restrict__ Yi = Y + plane;

    // ---- Phase 0: cooperative halo load (clamped) ----
    #pragma unroll 4
    for (int i = tid; i < IH_ * IW_; i += TW_) {
        int r  = i / IW_;
        int cc = i - r * IW_;
        int gy = min(iy0 + r,  H - 1);
        int gx = min(ix0 + cc, W - 1);
        int gi = gy * W + gx;
        sxy[r][cc] = make_float2(Xi[gi], Yi[gi]);
    }
    __syncthreads();

    const float G[KW] = {
        0.00102838f, 0.00759875f, 0.03600077f, 0.10936069f, 0.21300553f,
        0.26601174f,
        0.21300553f, 0.10936069f, 0.03600077f, 0.00759875f, 0.00102838f
    };
    const float C1 = 1e-4f;
    const float C2 = 9e-4f;

    ull   r01[KW];
    ull   r23[KW];
    float r4[KW];

    const int lx = tid;
    const int ox = ix0 + lx;
    const bool colOK = (ox < outW);
    float local = 0.f;

    #pragma unroll
    for (int r = 0; r < IH_; r++) {
        const ull* __restrict__ row =
            reinterpret_cast<const ull*>(&sxy[r][lx]);
        ull s01, s23; float s4;
        {
            ull v = row[0];
            ull gg = pk2(G[0], G[0]);
            s01 = mul2(gg, v);
            ull t = mul2(gg, v);
            s23 = mul2(t, v);
            float xv, yv, tl, th;
            up2(v, xv, yv); up2(t, tl, th);
            s4 = tl * yv;
            (void)xv; (void)th;
        }
        #pragma unroll
        for (int k = 1; k < KW; k++) {
            ull v = row[k];
            ull gg = pk2(G[k], G[k]);
            s01 = fma2(gg, v, s01);
            ull t = mul2(gg, v);
            s23 = fma2(t, v, s23);
            float xv, yv, tl, th;
            up2(v, xv, yv); up2(t, tl, th);
            s4 = fmaf(tl, yv, s4);
            (void)xv; (void)th;
        }
        r01[r % KW] = s01;
        r23[r % KW] = s23;
        r4[r % KW]  = s4;

        if (r >= KW - 1) {
            const int orow = r - (KW - 1);
            ull m01, m23; float m4;
            {
                int idx = orow % KW;
                ull gg = pk2(G[0], G[0]);
                m01 = mul2(gg, r01[idx]);
                m23 = mul2(gg, r23[idx]);
                m4  = G[0] * r4[idx];
            }
            #pragma unroll
            for (int k = 1; k < KW; k++) {
                int idx = (orow + k) % KW;
                ull gg = pk2(G[k], G[k]);
                m01 = fma2(gg, r01[idx], m01);
                m23 = fma2(gg, r23[idx], m23);
                m4  = fmaf(G[k], r4[idx], m4);
            }
            int oy = iy0 + orow;
            if (colOK && oy < outH) {
                float mu1, mu2, xx, yy;
                up2(m01, mu1, mu2);
                up2(m23, xx, yy);
                float s1q = xx - mu1 * mu1;
                float s2q = yy - mu2 * mu2;
                float s12 = m4 - mu1 * mu2;
                float cs = __fdividef(2.f * s12 + C2, s1q + s2q + C2);
                cs = fmaxf(cs, 0.f);
                if (LAST) {
                    float lum = __fdividef(2.f * mu1 * mu2 + C1,
                                           mu1 * mu1 + mu2 * mu2 + C1);
                    local = fmaf(lum, cs, local);
                } else {
                    local += cs;
                }
            }
        }
    }

    // ---- Fused 2x2 pool. Last tile row pools all remaining rows (<= IH_).
    if (POOL) {
        const int oW = W >> 1;
        const int oHp = H >> 1;
        const int pgy0 = iy0 >> 1;
        const int pgx0 = ix0 >> 1;
        constexpr int PW = TW_ / 2;
        const int tilesY = (int)(gridDim.x) / tilesX;
        const int nin = (ty == tilesY - 1) ? (H - iy0) : TH_;
        const int npool = nin >> 1;
        float* __restrict__ Xo = Xp + (size_t)(b * NC + c) * oW * oHp;
        float* __restrict__ Yo = Yp + (size_t)(b * NC + c) * oW * oHp;
        for (int idx = tid; idx < npool * PW; idx += TW_) {
            int py = idx / PW;
            int px = idx % PW;
            float2 a  = sxy[2 * py][2 * px];
            float2 bb = sxy[2 * py][2 * px + 1];
            float2 cc = sxy[2 * py + 1][2 * px];
            float2 dd = sxy[2 * py + 1][2 * px + 1];
            float xv = 0.25f * ((a.x + bb.x) + (cc.x + dd.x));
            float yv = 0.25f * ((a.y + bb.y) + (cc.y + dd.y));
            size_t o = (size_t)(pgy0 + py) * oW + (pgx0 + px);
            Xo[o] = xv;
            Yo[o] = yv;
        }
    }

    #pragma unroll
    for (int s = 16; s > 0; s >>= 1)
        local += __shfl_down_sync(0xffffffffu, local, s);
    if ((tid & 31) == 0) red[tid >> 5] = local;
    __syncthreads();
    if (tid == 0) {
        float t = 0.f;
        #pragma unroll
        for (int w = 0; w < NWARP; w++) t += red[w];
        atomicAdd(&g_acc[level * NB + b], (double)t);
    }
}

__global__ void finalize_kernel(float* __restrict__ out) {
    int b = threadIdx.x;
    if (b >= NB) return;
    const double counts[4] = {
        3.0 * 502.0 * 502.0,
        3.0 * 246.0 * 246.0,
        3.0 * 118.0 * 118.0,
        3.0 * 54.0  * 54.0
    };
    const double wraw[4] = {0.0448, 0.2856, 0.3001, 0.2363};
    const double wsum = 0.0448 + 0.2856 + 0.3001 + 0.2363;
    double s = 0.0;
    #pragma unroll
    for (int l = 0; l < 4; l++) {
        double v = g_acc[l * NB + b] / counts[l];
        v = v > 1e-8 ? v : 1e-8;
        s += (wraw[l] / wsum) * log(v);
    }
    out[b] = (float)(1.0 - exp(s));
}

extern "C" void kernel_launch(void* const* d_in, const int* in_sizes, int n_in,
                              void* d_out, int out_size)
{
    const float* X = (const float*)d_in[0];
    const float* Y = (const float*)d_in[1];
    float* out = (float*)d_out;
    (void)in_sizes; (void)n_in; (void)out_size;

    static float *pX1 = nullptr, *pY1 = nullptr, *pX2 = nullptr, *pY2 = nullptr,
                 *pX3 = nullptr, *pY3 = nullptr;
    if (!pX1) {
        cudaGetSymbolAddress((void**)&pX1, g_X1);
        cudaGetSymbolAddress((void**)&pY1, g_Y1);
        cudaGetSymbolAddress((void**)&pX2, g_X2);
        cudaGetSymbolAddress((void**)&pY2, g_Y2);
        cudaGetSymbolAddress((void**)&pX3, g_X3);
        cudaGetSymbolAddress((void**)&pY3, g_Y3);
    }

    zero_acc_kernel<<<1, 64>>>();

    // Level 0: 512 -> out 502, fused pool to 256. Tiles 128x22 (5 blocks/SM).
    {
        dim3 grid(4 * 23, NC, NB);     // tilesX=4, tilesY=23 (23*22=506)
        ssim_level_kernel<128, 22, false, true, 5><<<grid, 128>>>(
            X, Y, pX1, pY1, 512, 512, 502, 502, 4, 0);
    }
    // Level 1: 256 -> out 246, fused pool to 128. Tiles 128x22.
    {
        dim3 grid(2 * 12, NC, NB);     // tilesX=2, tilesY=12 (12*22=264)
        ssim_level_kernel<128, 22, false, true, 5><<<grid, 128>>>(
            pX1, pY1, pX2, pY2, 256, 256, 246, 246, 2, 1);
    }
    // Level 2: 128 -> out 118, fused pool to 64. Tiles 64x16, MINB=12
    // (R12-proven: 80 regs, 14.8us).
    {
        dim3 grid(2 * 8, NC, NB);
        ssim_level_kernel<64, 16, false, true, 12><<<grid, 64>>>(
            pX2, pY2, pX3, pY3, 128, 128, 118, 118, 2, 2);
    }
    // Level 3: 64 -> out 54, last (ssim map), no pool. Tiles 64x16, MINB=12.
    {
        dim3 grid(1 * 4, NC, NB);
        ssim_level_kernel<64, 16, true, false, 12><<<grid, 64>>>(
            pX3, pY3, nullptr, nullptr, 64, 64, 54, 54, 1, 3);
    }

    finalize_kernel<<<1, 32>>>(out);
}